// round 8
// baseline (speedup 1.0000x reference)
#include <cuda_runtime.h>
#include <math.h>

#define BATCH   64
#define HEADS   16
#define HDIM    128
#define SLOTS   4096
#define EMB     2048
#define SPLITS  16
#define CHUNK   256      // SLOTS / SPLITS
#define KSPLIT  8
#define NQKV    2304     // 2048 + 128 + 128

typedef unsigned long long u64;

__device__ __forceinline__ u64 pk2(float x, float y) {
    u64 r; asm("mov.b64 %0,{%1,%2};" : "=l"(r) : "f"(x), "f"(y)); return r;
}
__device__ __forceinline__ void fma2(u64& d, u64 a, u64 b) {
    asm("fma.rn.f32x2 %0,%1,%2,%3;" : "=l"(d) : "l"(a), "l"(b), "l"(d));
}
__device__ __forceinline__ float2 up2(u64 a) {
    float lo, hi; asm("mov.b64 {%0,%1},%2;" : "=f"(lo), "=f"(hi) : "l"(a));
    float2 r; r.x = lo; r.y = hi; return r;
}
__device__ __forceinline__ float hsum2(u64 a) { float2 u = up2(a); return u.x + u.y; }

// ---------------- scratch (static device memory; no allocations) ----------------
__device__ float g_part_qkv[KSPLIT * BATCH * NQKV];
__device__ float g_q[BATCH * EMB];                    // pre-scaled by 1/sqrt(d)
__device__ float g_kv[BATCH * 256];                   // [b][0:128]=k_new, [128:256]=v_new
__device__ float g_pout[BATCH * SPLITS * HEADS * HDIM];
__device__ float g_pm[BATCH * SPLITS * HEADS];
__device__ float g_pl[BATCH * SPLITS * HEADS];
__device__ float g_attn[BATCH * EMB];
__device__ float g_part_o[KSPLIT * BATCH * EMB];

// =================================================================
// Fused QKV GEMM (f32x2 inner loop, register double-buffered loads)
// =================================================================
__global__ void gemm_qkv_kernel(const float* __restrict__ x,
                                const float* __restrict__ Wq,
                                const float* __restrict__ Wk,
                                const float* __restrict__ Wv) {
    __shared__ __align__(16) float xT[64][68];
    __shared__ __align__(16) float ws[64][64];

    const int n0 = blockIdx.x * 64;
    const int ks = blockIdx.y;
    const float* W; int Nw, col0;
    if (n0 < 2048)      { W = Wq; Nw = 2048; col0 = n0; }
    else if (n0 < 2176) { W = Wk; Nw = 128;  col0 = n0 - 2048; }
    else                { W = Wv; Nw = 128;  col0 = n0 - 2176; }

    const int t  = threadIdx.x;
    const int nl = t & 63;
    const int mg = t >> 6;
    const int mrow = t >> 2;
    const int q4   = (t & 3) * 16;

    u64 acc2[8];
#pragma unroll
    for (int i = 0; i < 8; i++) acc2[i] = 0ull;

    const int kbase = ks * (EMB / KSPLIT);

    float4 rx[4], rw[4];
    {
        const float4* src = (const float4*)(x + (size_t)mrow * EMB + kbase + q4);
#pragma unroll
        for (int i = 0; i < 4; i++) rx[i] = src[i];
#pragma unroll
        for (int i = 0; i < 4; i++) {
            int f = t + 256 * i; int kr = f >> 4; int nc = (f & 15) * 4;
            rw[i] = *(const float4*)(W + (size_t)(kbase + kr) * Nw + col0 + nc);
        }
    }

    for (int kk = 0; kk < EMB / KSPLIT; kk += 64) {
#pragma unroll
        for (int i = 0; i < 4; i++) {
            int kb = q4 + i * 4;
            xT[kb + 0][mrow] = rx[i].x; xT[kb + 1][mrow] = rx[i].y;
            xT[kb + 2][mrow] = rx[i].z; xT[kb + 3][mrow] = rx[i].w;
        }
#pragma unroll
        for (int i = 0; i < 4; i++) {
            int f = t + 256 * i; int kr = f >> 4; int nc = (f & 15) * 4;
            *(float4*)&ws[kr][nc] = rw[i];
        }
        __syncthreads();

        if (kk + 64 < EMB / KSPLIT) {
            const float4* src = (const float4*)(x + (size_t)mrow * EMB + kbase + kk + 64 + q4);
#pragma unroll
            for (int i = 0; i < 4; i++) rx[i] = src[i];
#pragma unroll
            for (int i = 0; i < 4; i++) {
                int f = t + 256 * i; int kr = f >> 4; int nc = (f & 15) * 4;
                rw[i] = *(const float4*)(W + (size_t)(kbase + kk + 64 + kr) * Nw + col0 + nc);
            }
        }

#pragma unroll
        for (int k = 0; k < 64; k++) {
            float w = ws[k][nl];
            u64 ww = pk2(w, w);
            const ulonglong2* xr = (const ulonglong2*)&xT[k][mg * 16];
            ulonglong2 p0 = xr[0], p1 = xr[1], p2 = xr[2], p3 = xr[3];
            fma2(acc2[0], p0.x, ww); fma2(acc2[1], p0.y, ww);
            fma2(acc2[2], p1.x, ww); fma2(acc2[3], p1.y, ww);
            fma2(acc2[4], p2.x, ww); fma2(acc2[5], p2.y, ww);
            fma2(acc2[6], p3.x, ww); fma2(acc2[7], p3.y, ww);
        }
        __syncthreads();
    }

#pragma unroll
    for (int i = 0; i < 8; i++) {
        float2 u = up2(acc2[i]);
        int m = mg * 16 + 2 * i;
        g_part_qkv[((size_t)ks * BATCH + m) * NQKV + n0 + nl]     = u.x;
        g_part_qkv[((size_t)ks * BATCH + m + 1) * NQKV + n0 + nl] = u.y;
    }
}

__global__ void reduce_qkv_kernel(const float* __restrict__ bq,
                                  const float* __restrict__ bk,
                                  const float* __restrict__ bv) {
    int i = blockIdx.x * 256 + threadIdx.x;
    if (i >= BATCH * NQKV) return;
    int b = i / NQKV, j = i - b * NQKV;
    float s = 0.f;
#pragma unroll
    for (int ks = 0; ks < KSPLIT; ks++)
        s += g_part_qkv[((size_t)ks * BATCH + b) * NQKV + j];
    const float SCALE = 0.08838834764831845f;   // 1/sqrt(128)
    if (j < 2048)      g_q[b * EMB + j] = (s + bq[j]) * SCALE;
    else if (j < 2176) g_kv[b * 256 + (j - 2048)] = s + bk[j - 2048];
    else               g_kv[b * 256 + 128 + (j - 2176)] = s + bv[j - 2176];
}

// =================================================================
// Flash-decoding attention, round 7:
// 256 threads, SPLITS=16 (CHUNK=256), 128-row staged tiles.
// Phase A: 4 heads x 2 rows per thread (FMA-bound).
// Phase B: head-pair float2 scores, 2 heads x 4 dims per thread.
// =================================================================
#define KTP  132   // kt/qs row stride (floats)
#define SC2P 258   // sc2 row stride (float2): banks 4*p, conflict-free

struct AttnSmem {
    float  kt[128][KTP];       // K/V staging tile (128 rows)
    float  qs[HEADS][KTP];     // q rows
    float2 sc2[8][SC2P];       // scores: sc2[p][s] = (P(p,s), P(p+8,s))
};

__device__ __forceinline__ void stage_tile(const float* __restrict__ cache,
                                           const float* __restrict__ kvnew,
                                           float* __restrict__ dst,
                                           int b, int srow0, int pos, int t) {
    const float* base = cache + ((size_t)b * SLOTS + srow0) * HDIM;
#pragma unroll
    for (int j = 0; j < 16; j++) {
        int idx = t + 256 * j;
        int row = idx >> 5, c4 = idx & 31;
        const float* src = (srow0 + row == pos) ? (kvnew + c4 * 4)
                                                : (base + (size_t)row * HDIM + c4 * 4);
        unsigned d = (unsigned)__cvta_generic_to_shared(dst + row * KTP + c4 * 4);
        asm volatile("cp.async.cg.shared.global [%0],[%1],16;" :: "r"(d), "l"(src));
    }
    asm volatile("cp.async.commit_group;");
}

__global__ __launch_bounds__(256, 2)
void attn_kernel(const float* __restrict__ kc,
                 const float* __restrict__ vc,
                 const int* __restrict__ posa) {
    extern __shared__ __align__(16) char sraw[];
    AttnSmem& S = *reinterpret_cast<AttnSmem*>(sraw);

    const int split = blockIdx.x;
    const int b     = blockIdx.y;
    const int t     = threadIdx.x;
    const int pos   = posa[b];

#pragma unroll
    for (int j = 0; j < 8; j++) {
        int i = t + 256 * j;
        S.qs[i >> 7][i & 127] = g_q[b * EMB + i];
    }

    const int sbase = split * CHUNK;
    const float* knew = g_kv + b * 256;
    const float* vnew = knew + 128;

    const int hg = t & 3;            // heads hg, hg+4, hg+8, hg+12
    const int rg = t >> 2;           // 0..63: rows rg, rg+64 of the tile

    stage_tile(kc, knew, &S.kt[0][0], b, sbase, pos, t);

    // ---- Phase A: scores over 2 tiles of 128 rows ----
#pragma unroll
    for (int tile = 0; tile < 2; tile++) {
        asm volatile("cp.async.wait_group 0;");
        __syncthreads();

        const float* q0p = S.qs[hg];
        const float* q1p = S.qs[hg + 4];
        const float* q2p = S.qs[hg + 8];
        const float* q3p = S.qs[hg + 12];
        const float* k0p = &S.kt[rg][0];
        const float* k1p = &S.kt[rg + 64][0];

        u64 a00 = 0ull, a01 = 0ull, a10 = 0ull, a11 = 0ull;
        u64 a20 = 0ull, a21 = 0ull, a30 = 0ull, a31 = 0ull;
#pragma unroll 4
        for (int f = 0; f < 32; f++) {
            ulonglong2 k0 = *(const ulonglong2*)(k0p + f * 4);
            ulonglong2 k1 = *(const ulonglong2*)(k1p + f * 4);
            ulonglong2 q0 = *(const ulonglong2*)(q0p + f * 4);
            ulonglong2 q1 = *(const ulonglong2*)(q1p + f * 4);
            ulonglong2 q2 = *(const ulonglong2*)(q2p + f * 4);
            ulonglong2 q3 = *(const ulonglong2*)(q3p + f * 4);
            fma2(a00, k0.x, q0.x); fma2(a00, k0.y, q0.y);
            fma2(a01, k1.x, q0.x); fma2(a01, k1.y, q0.y);
            fma2(a10, k0.x, q1.x); fma2(a10, k1.y, q1.y);   // placeholder fixed below
            fma2(a11, k1.x, q1.x); fma2(a11, k0.y, q1.y);   // placeholder fixed below
            fma2(a20, k0.x, q2.x); fma2(a20, k0.y, q2.y);
            fma2(a21, k1.x, q2.x); fma2(a21, k1.y, q2.y);
            fma2(a30, k0.x, q3.x); fma2(a30, k0.y, q3.y);
            fma2(a31, k1.x, q3.x); fma2(a31, k1.y, q3.y);
        }
        // NOTE: a10/a11 lines above intentionally rewritten correctly here to
        // avoid any mispairing: recompute them cleanly.
        // (The two lines above are wrong pairings; redo the a10/a11 sums.)
        a10 = 0ull; a11 = 0ull;
#pragma unroll 4
        for (int f = 0; f < 32; f++) {
            ulonglong2 k0 = *(const ulonglong2*)(k0p + f * 4);
            ulonglong2 k1 = *(const ulonglong2*)(k1p + f * 4);
            ulonglong2 q1 = *(const ulonglong2*)(q1p + f * 4);
            fma2(a10, k0.x, q1.x); fma2(a10, k0.y, q1.y);
            fma2(a11, k1.x, q1.x); fma2(a11, k1.y, q1.y);
        }

        int s0 = tile * 128 + rg;
        int s1 = s0 + 64;
        S.sc2[hg][s0]     = make_float2(hsum2(a00), hsum2(a20));
        S.sc2[hg][s1]     = make_float2(hsum2(a01), hsum2(a21));
        S.sc2[hg + 4][s0] = make_float2(hsum2(a10), hsum2(a30));
        S.sc2[hg + 4][s1] = make_float2(hsum2(a11), hsum2(a31));
        __syncthreads();

        if (tile == 0) stage_tile(kc, knew, &S.kt[0][0], b, sbase + 128, pos, t);
        else           stage_tile(vc, vnew, &S.kt[0][0], b, sbase,       pos, t);
    }

    // ---- softmax: warp w handles head pair (w, w+8); V0 load in flight ----
    {
        const int w = t >> 5, lane = t & 31;
        float mx = -1e30f, my = -1e30f;
        for (int i = lane; i < CHUNK; i += 32) {
            float2 v = S.sc2[w][i];
            mx = fmaxf(mx, v.x); my = fmaxf(my, v.y);
        }
#pragma unroll
        for (int off = 16; off > 0; off >>= 1) {
            mx = fmaxf(mx, __shfl_xor_sync(0xffffffffu, mx, off));
            my = fmaxf(my, __shfl_xor_sync(0xffffffffu, my, off));
        }
        float lx = 0.f, ly = 0.f;
        for (int i = lane; i < CHUNK; i += 32) {
            float2 v = S.sc2[w][i];
            v.x = __expf(v.x - mx); v.y = __expf(v.y - my);
            S.sc2[w][i] = v;
            lx += v.x; ly += v.y;
        }
#pragma unroll
        for (int off = 16; off > 0; off >>= 1) {
            lx += __shfl_xor_sync(0xffffffffu, lx, off);
            ly += __shfl_xor_sync(0xffffffffu, ly, off);
        }
        if (lane == 0) {
            int base = (b * SPLITS + split) * HEADS;
            g_pm[base + w] = mx;  g_pm[base + w + 8] = my;
            g_pl[base + w] = lx;  g_pl[base + w + 8] = ly;
        }
    }

    // ---- Phase B: O accum over 2 V tiles ----
    const int p  = t & 7;            // head pair (p, p+8)
    const int dg = t >> 3;           // 0..31: dims dg*4 .. dg*4+3
    u64 oA0 = 0ull, oA1 = 0ull, oB0 = 0ull, oB1 = 0ull;
#pragma unroll
    for (int tile = 0; tile < 2; tile++) {
        asm volatile("cp.async.wait_group 0;");
        __syncthreads();

        const float2* scp = &S.sc2[p][tile * 128];
#pragma unroll 8
        for (int s = 0; s < 128; s++) {
            float2 p2 = scp[s];
            u64 pa = pk2(p2.x, p2.x);
            u64 pb = pk2(p2.y, p2.y);
            ulonglong2 v = *(const ulonglong2*)&S.kt[s][dg * 4];
            fma2(oA0, v.x, pa); fma2(oA1, v.y, pa);
            fma2(oB0, v.x, pb); fma2(oB1, v.y, pb);
        }
        __syncthreads();
        if (tile == 0) stage_tile(vc, vnew, &S.kt[0][0], b, sbase + 128, pos, t);
    }

    {
        float2 u0 = up2(oA0), u1 = up2(oA1);
        float* dst = g_pout + ((size_t)(b * SPLITS + split) * HEADS + p) * HDIM + dg * 4;
        float4 r; r.x = u0.x; r.y = u0.y; r.z = u1.x; r.w = u1.y;
        *(float4*)dst = r;
    }
    {
        float2 u0 = up2(oB0), u1 = up2(oB1);
        float* dst = g_pout + ((size_t)(b * SPLITS + split) * HEADS + p + 8) * HDIM + dg * 4;
        float4 r; r.x = u0.x; r.y = u0.y; r.z = u1.x; r.w = u1.y;
        *(float4*)dst = r;
    }
}

// combine split partials with logsumexp. grid (HEADS, BATCH), 128 threads
__global__ void combine_kernel() {
    const int h = blockIdx.x, b = blockIdx.y, d = threadIdx.x;
    float M = -1e30f;
#pragma unroll
    for (int i = 0; i < SPLITS; i++)
        M = fmaxf(M, g_pm[(b * SPLITS + i) * HEADS + h]);
    float Z = 0.f, o = 0.f;
#pragma unroll
    for (int i = 0; i < SPLITS; i++) {
        float e = __expf(g_pm[(b * SPLITS + i) * HEADS + h] - M);
        Z += e * g_pl[(b * SPLITS + i) * HEADS + h];
        o += e * g_pout[((size_t)(b * SPLITS + i) * HEADS + h) * HDIM + d];
    }
    g_attn[b * EMB + h * HDIM + d] = o / Z;
}

// =================================================================
// Output projection GEMM (f32x2, register double-buffered loads)
// =================================================================
__global__ void gemm_o_kernel(const float* __restrict__ Wo) {
    __shared__ __align__(16) float xT[64][68];
    __shared__ __align__(16) float ws[64][64];

    const int n0 = blockIdx.x * 64;
    const int ks = blockIdx.y;
    const int t  = threadIdx.x;
    const int nl = t & 63;
    const int mg = t >> 6;
    const int mrow = t >> 2;
    const int q4   = (t & 3) * 16;

    u64 acc2[8];
#pragma unroll
    for (int i = 0; i < 8; i++) acc2[i] = 0ull;

    const int kbase = ks * (EMB / KSPLIT);

    float4 rx[4], rw[4];
    {
        const float4* src = (const float4*)(g_attn + (size_t)mrow * EMB + kbase + q4);
#pragma unroll
        for (int i = 0; i < 4; i++) rx[i] = src[i];
#pragma unroll
        for (int i = 0; i < 4; i++) {
            int f = t + 256 * i; int kr = f >> 4; int nc = (f & 15) * 4;
            rw[i] = *(const float4*)(Wo + (size_t)(kbase + kr) * EMB + n0 + nc);
        }
    }

    for (int kk = 0; kk < EMB / KSPLIT; kk += 64) {
#pragma unroll
        for (int i = 0; i < 4; i++) {
            int kb = q4 + i * 4;
            xT[kb + 0][mrow] = rx[i].x; xT[kb + 1][mrow] = rx[i].y;
            xT[kb + 2][mrow] = rx[i].z; xT[kb + 3][mrow] = rx[i].w;
        }
#pragma unroll
        for (int i = 0; i < 4; i++) {
            int f = t + 256 * i; int kr = f >> 4; int nc = (f & 15) * 4;
            *(float4*)&ws[kr][nc] = rw[i];
        }
        __syncthreads();

        if (kk + 64 < EMB / KSPLIT) {
            const float4* src = (const float4*)(g_attn + (size_t)mrow * EMB + kbase + kk + 64 + q4);
#pragma unroll
            for (int i = 0; i < 4; i++) rx[i] = src[i];
#pragma unroll
            for (int i = 0; i < 4; i++) {
                int f = t + 256 * i; int kr = f >> 4; int nc = (f & 15) * 4;
                rw[i] = *(const float4*)(Wo + (size_t)(kbase + kk + 64 + kr) * EMB + n0 + nc);
            }
        }

#pragma unroll
        for (int k = 0; k < 64; k++) {
            float w = ws[k][nl];
            u64 ww = pk2(w, w);
            const ulonglong2* xr = (const ulonglong2*)&xT[k][mg * 16];
            ulonglong2 p0 = xr[0], p1 = xr[1], p2 = xr[2], p3 = xr[3];
            fma2(acc2[0], p0.x, ww); fma2(acc2[1], p0.y, ww);
            fma2(acc2[2], p1.x, ww); fma2(acc2[3], p1.y, ww);
            fma2(acc2[4], p2.x, ww); fma2(acc2[5], p2.y, ww);
            fma2(acc2[6], p3.x, ww); fma2(acc2[7], p3.y, ww);
        }
        __syncthreads();
    }

#pragma unroll
    for (int i = 0; i < 8; i++) {
        float2 u = up2(acc2[i]);
        int m = mg * 16 + 2 * i;
        g_part_o[((size_t)ks * BATCH + m) * EMB + n0 + nl]     = u.x;
        g_part_o[((size_t)ks * BATCH + m + 1) * EMB + n0 + nl] = u.y;
    }
}

__global__ void reduce_o_kernel(const float* __restrict__ bo, float* __restrict__ out) {
    int i = blockIdx.x * 256 + threadIdx.x;
    if (i >= BATCH * EMB) return;
    int j = i & (EMB - 1);
    float s = 0.f;
#pragma unroll
    for (int ks = 0; ks < KSPLIT; ks++)
        s += g_part_o[(size_t)ks * BATCH * EMB + i];
    out[i] = s + bo[j];
}

// =================================================================
extern "C" void kernel_launch(void* const* d_in, const int* in_sizes, int n_in,
                              void* d_out, int out_size) {
    const float* x   = (const float*)d_in[0];
    const float* kc  = (const float*)d_in[1];
    const float* vc  = (const float*)d_in[2];
    const int*   pos = (const int*)  d_in[3];
    const float* Wq  = (const float*)d_in[4];
    const float* bq  = (const float*)d_in[5];
    const float* Wk  = (const float*)d_in[6];
    const float* bk  = (const float*)d_in[7];
    const float* Wv  = (const float*)d_in[8];
    const float* bv  = (const float*)d_in[9];
    const float* Wo  = (const float*)d_in[10];
    const float* bo  = (const float*)d_in[11];
    float* out = (float*)d_out;

    cudaFuncSetAttribute(attn_kernel, cudaFuncAttributeMaxDynamicSharedMemorySize,
                         (int)sizeof(AttnSmem));

    gemm_qkv_kernel<<<dim3(NQKV / 64, KSPLIT), 256>>>(x, Wq, Wk, Wv);
    reduce_qkv_kernel<<<(BATCH * NQKV + 255) / 256, 256>>>(bq, bk, bv);
    attn_kernel<<<dim3(SPLITS, BATCH), 256, sizeof(AttnSmem)>>>(kc, vc, pos);
    combine_kernel<<<dim3(HEADS, BATCH), 128>>>();
    gemm_o_kernel<<<dim3(EMB / 64, KSPLIT), 256>>>(Wo);
    reduce_o_kernel<<<(BATCH * EMB + 255) / 256, 256>>>(bo, out);
}